// round 8
// baseline (speedup 1.0000x reference)
#include <cuda_runtime.h>
#include <cstdint>
typedef unsigned long long ull;
#define Nn 30000
#define Ee 480000

__device__ __align__(16) float d_h[Nn*128];
__device__ __align__(16) float d_P1[Nn*128];
__device__ __align__(16) float d_P2[Nn*128];
__device__ __align__(16) float d_agg[Nn*128];
__device__ __align__(16) float d_qin[Nn*128];
__device__ float d_radial[Ee];
__device__ float d_xacc[Nn*3];
__device__ __align__(16) float d_Wl[2*16384];
__device__ __align__(16) float2 d_qb[20*16384];
__device__ int d_g[128];

__device__ __forceinline__ ull pk2(float lo,float hi){ull r;asm("mov.b64 %0,{%1,%2};":"=l"(r):"f"(lo),"f"(hi));return r;}
__device__ __forceinline__ void up2(ull v,float&lo,float&hi){asm("mov.b64 {%0,%1},%2;":"=f"(lo),"=f"(hi):"l"(v));}
__device__ __forceinline__ void fma2(ull&d,ull a,ull b){asm("fma.rn.f32x2 %0,%1,%2,%0;":"+l"(d):"l"(a),"l"(b));}
__device__ __forceinline__ float siluf(float v){return v/(1.f+__expf(-v));}
__device__ __forceinline__ void red2(float*p,float a,float b){asm volatile("red.global.add.v2.f32 [%0],{%1,%2};"::"l"(p),"f"(a),"f"(b):"memory");}
__device__ __forceinline__ float2 cmul(float2 a,float2 b){return make_float2(a.x*b.x-a.y*b.y,a.x*b.y+a.y*b.x);}

__global__ void k_setup_perm(){
  int g[128],f[128],t2[128];
  for(int i=0;i<128;i++)g[i]=i;
  for(int p=0;p<7;p++){
    int c=p,t=(p==6)?0:p+1;
    for(int i=0;i<128;i++){int cb=(i>>(6-c))&1;f[i]=i^(cb<<(6-t));}
    for(int i=0;i<128;i++)t2[i]=g[f[i]];
    for(int i=0;i<128;i++)g[i]=t2[i];
  }
  for(int i=0;i<128;i++)d_g[i]=g[i];
}

__global__ void k_build(const float* __restrict__ A_re,const float* __restrict__ A_im,const float* __restrict__ coeffs){
  __shared__ float2 G[2][2]; __shared__ int gs[128];
  int u=blockIdx.x;
  if(threadIdx.x==0){
    float a=coeffs[u*2],b=coeffs[u*2+1];
    float ca=cosf(.5f*a),sa=sinf(.5f*a),cb=cosf(.5f*b),sb=sinf(.5f*b);
    G[0][0]=make_float2(cb*ca, sb*sa);
    G[0][1]=make_float2(-sb*ca,-cb*sa);
    G[1][0]=make_float2( sb*ca,-cb*sa);
    G[1][1]=make_float2(cb*ca,-sb*sa);
  }
  if(threadIdx.x<128)gs[threadIdx.x]=d_g[threadIdx.x];
  __syncthreads();
  const float* Ar=A_re+(size_t)u*16384; const float* Ai=A_im+(size_t)u*16384;
  float2* C =d_qb+(size_t)u*16384;
  float2* Xa=d_qb+(size_t)(4+u)*16384;
  float2* GP=d_qb+(size_t)(16+u)*16384;
  for(int t=threadIdx.x;t<16384;t+=blockDim.x){
    int r=t>>7,c=t&127;
    float2 cc;
    cc.x=Ar[r*128+c]+Ar[c*128+r];
    cc.y=Ai[r*128+c]-Ai[c*128+r]+((r==c)?1.f:0.f);
    C[t]=cc;
    Xa[t]=make_float2(0.f,(r==c)?-1.f:0.f);
    int gi=gs[c];
    float2 p=make_float2(1.f,0.f);
    #pragma unroll
    for(int b_=0;b_<7;b_++)p=cmul(p,G[(gi>>b_)&1][(r>>b_)&1]);
    GP[t]=p;
  }
}

// complex 128x128 GEMM on d_qb slots. mode 1: OUT = 2*A - A@B
__global__ void cgemm(int osl,int ost,int asl,int ast,int bsl,int bst,int mode){
  int u=blockIdx.y;
  const float2* Au=d_qb+(size_t)(asl+u*ast)*16384;
  const float2* Bu=d_qb+(size_t)(bsl+u*bst)*16384;
  float2* Ou=d_qb+(size_t)(osl+u*ost)*16384;
  int idx=blockIdx.x*256+threadIdx.x; int r=idx>>7,c=idx&127;
  float2 acc=make_float2(0.f,0.f);
  #pragma unroll 4
  for(int k=0;k<128;k++){
    float2 a=Au[r*128+k],b=Bu[k*128+c];
    acc.x=fmaf(a.x,b.x,acc.x); acc.x=fmaf(-a.y,b.y,acc.x);
    acc.y=fmaf(a.x,b.y,acc.y); acc.y=fmaf(a.y,b.x,acc.y);
  }
  if(mode==1){float2 xa=Au[r*128+c];acc.x=2.f*xa.x-acc.x;acc.y=2.f*xa.y-acc.y;}
  Ou[idx]=acc;
}

__global__ void k_qT(){
  int u=blockIdx.y;
  const float2* X=d_qb+(size_t)(8+u)*16384;
  float2* Q=d_qb+(size_t)(12+u)*16384;
  int t=blockIdx.x*256+threadIdx.x; int r=t>>7,c=t&127;
  float2 xv=X[c*128+r];
  Q[t]=make_float2(((r==c)?1.f:0.f)+2.f*xv.y,-2.f*xv.x);
}

__global__ void k_Wl(const float* __restrict__ dec_w){
  int k=blockIdx.x,l=blockIdx.y,c=threadIdx.x;
  const float2* L=d_qb+(size_t)(16+l)*16384;
  const float* dw=dec_w+(size_t)l*16384;
  float s=0.f;
  for(int i=0;i<128;i++)s=fmaf(L[k*128+i].x,dw[i*128+c],s);
  d_Wl[l*16384+k*128+c]=s;
}

__global__ void k_radial(const int* __restrict__ ei,const float* __restrict__ x){
  int e=blockIdx.x*256+threadIdx.x;
  int r=ei[e],c=ei[Ee+e];
  float dx=x[r*3]-x[c*3],dy=x[r*3+1]-x[c*3+1],dz=x[r*3+2]-x[c*3+2];
  d_radial[e]=dx*dx+dy*dy+dz*dz;
}

__global__ void k_norm(){
  int row=blockIdx.x*8+(threadIdx.x>>5),lane=threadIdx.x&31;
  float4* p=(float4*)(d_qin+(size_t)row*128);
  float4 v=p[lane];
  float s=v.x*v.x+v.y*v.y+v.z*v.z+v.w*v.w;
  #pragma unroll
  for(int o=16;o;o>>=1)s+=__shfl_xor_sync(0xffffffffu,s,o);
  float inv=rsqrtf(s+1e-12f);
  v.x*=inv;v.y*=inv;v.z*=inv;v.w*=inv;
  p[lane]=v;
}

__global__ void k_finx(const float* __restrict__ x,float* __restrict__ o){
  int i=blockIdx.x*256+threadIdx.x;
  if(i<Nn*3)o[i]=x[i]+d_xacc[i];
}

#define NG_SMEM (66560+33792+512)
// out = [accum?out:0] + A@W + bias
__global__ __launch_bounds__(256) void node_gemm(float* __restrict__ out,const float* __restrict__ A,
    const float* __restrict__ W,const float* __restrict__ bias,int accum){
  extern __shared__ float sm[];
  ull* Ws=(ull*)sm;
  float* As=sm+16640;
  float* bs=As+8448;
  int tid=threadIdx.x,n0=blockIdx.x*64;
  for(int t=tid;t<8192;t+=256){int k=t>>6,jp=t&63;Ws[k*65+jp]=pk2(W[k*128+jp*2],W[k*128+jp*2+1]);}
  if(tid<128)bs[tid]=bias?bias[tid]:0.f;
  for(int t=tid;t<2048;t+=256){
    int rr=t>>5,c4=(t&31)*4,n=n0+rr; if(n>=Nn)n=Nn-1;
    float4 v=*(const float4*)&A[(size_t)n*128+c4];
    *(float4*)&As[rr*132+c4]=v;
  }
  __syncthreads();
  int cg=tid&15,rg=tid>>4;
  ull acc[4][4];
  #pragma unroll
  for(int i=0;i<4;i++)for(int j=0;j<4;j++)acc[i][j]=0ULL;
  #pragma unroll 4
  for(int k=0;k<128;k++){
    ull b0=Ws[k*65+cg],b1=Ws[k*65+cg+16],b2=Ws[k*65+cg+32],b3=Ws[k*65+cg+48];
    #pragma unroll
    for(int i=0;i<4;i++){
      float a=As[(rg*4+i)*132+k]; ull aa=pk2(a,a);
      fma2(acc[i][0],aa,b0);fma2(acc[i][1],aa,b1);fma2(acc[i][2],aa,b2);fma2(acc[i][3],aa,b3);
    }
  }
  #pragma unroll
  for(int i=0;i<4;i++){
    int n=n0+rg*4+i; if(n>=Nn)continue;
    float* op=out+(size_t)n*128;
    #pragma unroll
    for(int j=0;j<4;j++){
      int c0=2*(cg+16*j);
      float lo,hi;up2(acc[i][j],lo,hi);
      lo+=bs[c0];hi+=bs[c0+1];
      if(accum){lo+=op[c0];hi+=op[c0+1];}
      op[c0]=lo;op[c0+1]=hi;
    }
  }
}

#define KE_SMEM (104192)
// mode 0: agg += silu(silu(m1)@W2+b2)/100 ; mode 1: coord head -> d_xacc
__global__ __launch_bounds__(256) void k_edge(const int* __restrict__ ei,const float* __restrict__ ea,
    const float* __restrict__ wre,const float* __restrict__ b1,const float* __restrict__ W2,
    const float* __restrict__ b2,const float* __restrict__ cw3,const float* __restrict__ x,int mode){
  extern __shared__ float sm[];
  ull* W2s=(ull*)sm;
  float* m1s=sm+16640;
  float* swr=m1s+8448; float* swe=swr+128; float* sb1=swe+128; float* sb2=sb1+128; float* scw=sb2+128;
  float* srad=scw+128; float* sea=srad+64; float* tdot=sea+64;
  int* srow=(int*)(tdot+64); int* scol=srow+64;
  int tid=threadIdx.x,e0=blockIdx.x*64;
  for(int t=tid;t<8192;t+=256){int k=t>>6,jp=t&63;W2s[k*65+jp]=pk2(W2[k*128+jp*2],W2[k*128+jp*2+1]);}
  if(tid<128){swr[tid]=wre[tid];swe[tid]=wre[128+tid];sb1[tid]=b1[tid];sb2[tid]=b2[tid];scw[tid]=mode?cw3[tid]:0.f;}
  if(tid<64){int e=e0+tid;srow[tid]=ei[e];scol[tid]=ei[Ee+e];srad[tid]=d_radial[e];sea[tid]=ea[e];tdot[tid]=0.f;}
  __syncthreads();
  for(int t=tid;t<2048;t+=256){
    int e=t>>5,c4=(t&31)*4;
    float4 p1=*(const float4*)&d_P1[(size_t)srow[e]*128+c4];
    float4 p2=*(const float4*)&d_P2[(size_t)scol[e]*128+c4];
    float r_=srad[e],w_=sea[e];
    float4 o;
    o.x=siluf(p1.x+p2.x+r_*swr[c4  ]+w_*swe[c4  ]+sb1[c4  ]);
    o.y=siluf(p1.y+p2.y+r_*swr[c4+1]+w_*swe[c4+1]+sb1[c4+1]);
    o.z=siluf(p1.z+p2.z+r_*swr[c4+2]+w_*swe[c4+2]+sb1[c4+2]);
    o.w=siluf(p1.w+p2.w+r_*swr[c4+3]+w_*swe[c4+3]+sb1[c4+3]);
    *(float4*)&m1s[e*132+c4]=o;
  }
  __syncthreads();
  int cg=tid&15,rg=tid>>4;
  ull acc[4][4];
  #pragma unroll
  for(int i=0;i<4;i++)for(int j=0;j<4;j++)acc[i][j]=0ULL;
  #pragma unroll 4
  for(int k=0;k<128;k++){
    ull b0=W2s[k*65+cg],b1_=W2s[k*65+cg+16],b2_=W2s[k*65+cg+32],b3_=W2s[k*65+cg+48];
    #pragma unroll
    for(int i=0;i<4;i++){
      float a=m1s[(rg*4+i)*132+k]; ull aa=pk2(a,a);
      fma2(acc[i][0],aa,b0);fma2(acc[i][1],aa,b1_);fma2(acc[i][2],aa,b2_);fma2(acc[i][3],aa,b3_);
    }
  }
  if(mode==0){
    #pragma unroll
    for(int i=0;i<4;i++){
      float* ap=d_agg+(size_t)srow[rg*4+i]*128;
      #pragma unroll
      for(int j=0;j<4;j++){
        int c0=2*(cg+16*j);
        float lo,hi;up2(acc[i][j],lo,hi);
        lo=siluf(lo+sb2[c0])*0.01f; hi=siluf(hi+sb2[c0+1])*0.01f;
        red2(ap+c0,lo,hi);
      }
    }
  }else{
    #pragma unroll
    for(int i=0;i<4;i++){
      float p=0.f;
      #pragma unroll
      for(int j=0;j<4;j++){
        int c0=2*(cg+16*j);
        float lo,hi;up2(acc[i][j],lo,hi);
        p+=siluf(lo+sb2[c0])*scw[c0]+siluf(hi+sb2[c0+1])*scw[c0+1];
      }
      atomicAdd(&tdot[rg*4+i],p);
    }
    __syncthreads();
    if(tid<64){
      int row=srow[tid],col=scol[tid];
      float dx=x[row*3]-x[col*3],dy=x[row*3+1]-x[col*3+1],dz=x[row*3+2]-x[col*3+2];
      float inv=1.f/(sqrtf(srad[tid]+1e-8f)+1.f);
      float tv=tdot[tid]*0.01f*inv;
      atomicAdd(&d_xacc[row*3  ],dx*tv);
      atomicAdd(&d_xacc[row*3+1],dy*tv);
      atomicAdd(&d_xacc[row*3+2],dz*tv);
    }
  }
}

extern "C" void kernel_launch(void* const* d_in,const int* in_sizes,int n_in,void* d_out,int out_size){
  const float* h=(const float*)d_in[0];
  const float* x=(const float*)d_in[1];
  const int* ei=(const int*)d_in[2];
  const float* ea=(const float*)d_in[3];
  const float* e_w1=(const float*)d_in[4];
  const float* e_b1=(const float*)d_in[5];
  const float* e_w2=(const float*)d_in[6];
  const float* e_b2=(const float*)d_in[7];
  const float* enc_w=(const float*)d_in[8];
  const float* enc_b=(const float*)d_in[9];
  const float* coeffs=(const float*)d_in[10];
  const float* A_re=(const float*)d_in[11];
  const float* A_im=(const float*)d_in[12];
  const float* dec_w=(const float*)d_in[13];
  const float* dec_b=(const float*)d_in[14];
  const float* c_w1=(const float*)d_in[15];
  const float* c_b1=(const float*)d_in[16];
  const float* c_w2=(const float*)d_in[17];
  const float* c_b2=(const float*)d_in[18];
  const float* c_w3=(const float*)d_in[19];
  float* out=(float*)d_out;

  cudaFuncSetAttribute(node_gemm,cudaFuncAttributeMaxDynamicSharedMemorySize,NG_SMEM);
  cudaFuncSetAttribute(k_edge,cudaFuncAttributeMaxDynamicSharedMemorySize,KE_SMEM);

  float *ph,*pP1,*pP2,*pagg,*pqin,*pWl,*pxacc;
  cudaGetSymbolAddress((void**)&ph,d_h);
  cudaGetSymbolAddress((void**)&pP1,d_P1);
  cudaGetSymbolAddress((void**)&pP2,d_P2);
  cudaGetSymbolAddress((void**)&pagg,d_agg);
  cudaGetSymbolAddress((void**)&pqin,d_qin);
  cudaGetSymbolAddress((void**)&pWl,d_Wl);
  cudaGetSymbolAddress((void**)&pxacc,d_xacc);

  // ---- quantum setup: Wl[l] = Re(T_{l,0} @ T_{l,1}) @ dec_w[l] ----
  k_setup_perm<<<1,1>>>();
  k_build<<<4,256>>>(A_re,A_im,coeffs);
  int cur=4,nxt=8;
  for(int it=0;it<5;it++){
    cgemm<<<dim3(64,4),256>>>(12,1, 0,1, cur,1, 0);  // E = C@X
    cgemm<<<dim3(64,4),256>>>(nxt,1, cur,1, 12,1, 1);// Xn = 2X - X@E
    int t_=cur;cur=nxt;nxt=t_;
  }
  k_qT<<<dim3(64,4),256>>>();
  cgemm<<<dim3(64,4),256>>>(0,1, 12,1, 16,1, 0);     // T_u = qT @ GP
  cgemm<<<dim3(64,2),256>>>(16,1, 0,2, 1,2, 0);      // L_l = T_{2l} @ T_{2l+1}
  k_Wl<<<dim3(128,2),128>>>(dec_w);

  // ---- main ----
  cudaMemcpyAsync(ph,h,(size_t)Nn*128*4,cudaMemcpyDeviceToDevice);
  k_radial<<<1875,256>>>(ei,x);
  for(int l=0;l<2;l++){
    const float* w1=e_w1+(size_t)l*258*128;
    node_gemm<<<469,256,NG_SMEM>>>(pP1,ph,w1,nullptr,0);
    node_gemm<<<469,256,NG_SMEM>>>(pP2,ph,w1+16384,nullptr,0);
    cudaMemsetAsync(pagg,0,(size_t)Nn*128*4);
    k_edge<<<7500,256,KE_SMEM>>>(ei,ea,w1+256*128,e_b1+l*128,e_w2+(size_t)l*16384,e_b2+l*128,nullptr,nullptr,0);
    node_gemm<<<469,256,NG_SMEM>>>(pqin,ph,enc_w+(size_t)l*256*128,nullptr,0);
    node_gemm<<<469,256,NG_SMEM>>>(pqin,pagg,enc_w+(size_t)l*256*128+16384,enc_b+l*128,1);
    k_norm<<<3750,256>>>();
    node_gemm<<<469,256,NG_SMEM>>>(ph,pqin,pWl+(size_t)l*16384,dec_b+l*128,1);
  }
  node_gemm<<<469,256,NG_SMEM>>>(pP1,ph,c_w1,nullptr,0);
  node_gemm<<<469,256,NG_SMEM>>>(pP2,ph,c_w1+16384,nullptr,0);
  cudaMemsetAsync(pxacc,0,(size_t)Nn*3*4);
  k_edge<<<7500,256,KE_SMEM>>>(ei,ea,c_w1+256*128,c_b1,c_w2,c_b2,c_w3,x,1);
  cudaMemcpyAsync(out,ph,(size_t)Nn*128*4,cudaMemcpyDeviceToDevice);
  k_finx<<<352,256>>>(x,out+(size_t)Nn*128);
}

// round 9
// speedup vs baseline: 1.0368x; 1.0368x over previous
#include <cuda_runtime.h>
#include <cstdint>
typedef unsigned long long ull;
#define Nn 30000
#define Ee 480000

__device__ __align__(16) float d_h[Nn*128];
__device__ __align__(16) float d_P1[Nn*128];
__device__ __align__(16) float d_P2[Nn*128];
__device__ __align__(16) float d_agg[Nn*128];
__device__ __align__(16) float d_qin[Nn*128];
__device__ float d_radial[Ee];
__device__ float d_xacc[Nn*3];
__device__ __align__(16) float d_Wl[2*16384];
__device__ __align__(16) float2 d_qb[20*16384];
__device__ int d_g[128];

__device__ __forceinline__ ull pk2(float lo,float hi){ull r;asm("mov.b64 %0,{%1,%2};":"=l"(r):"f"(lo),"f"(hi));return r;}
__device__ __forceinline__ void up2(ull v,float&lo,float&hi){asm("mov.b64 {%0,%1},%2;":"=f"(lo),"=f"(hi):"l"(v));}
__device__ __forceinline__ void fma2(ull&d,ull a,ull b){asm("fma.rn.f32x2 %0,%1,%2,%0;":"+l"(d):"l"(a),"l"(b));}
__device__ __forceinline__ float siluf(float v){return v/(1.f+__expf(-v));}
__device__ __forceinline__ void red2(float*p,float a,float b){asm volatile("red.global.add.v2.f32 [%0],{%1,%2};"::"l"(p),"f"(a),"f"(b):"memory");}
__device__ __forceinline__ float2 cmul(float2 a,float2 b){return make_float2(a.x*b.x-a.y*b.y,a.x*b.y+a.y*b.x);}
__device__ __forceinline__ void cfma(float2&acc,float2 a,float2 b){
  acc.x=fmaf(a.x,b.x,acc.x);acc.x=fmaf(-a.y,b.y,acc.x);
  acc.y=fmaf(a.x,b.y,acc.y);acc.y=fmaf(a.y,b.x,acc.y);
}

__global__ void k_setup_perm(){
  int g[128],f[128],t2[128];
  for(int i=0;i<128;i++)g[i]=i;
  for(int p=0;p<7;p++){
    int c=p,t=(p==6)?0:p+1;
    for(int i=0;i<128;i++){int cb=(i>>(6-c))&1;f[i]=i^(cb<<(6-t));}
    for(int i=0;i<128;i++)t2[i]=g[f[i]];
    for(int i=0;i<128;i++)g[i]=t2[i];
  }
  for(int i=0;i<128;i++)d_g[i]=g[i];
}

__global__ void k_build(const float* __restrict__ A_re,const float* __restrict__ A_im,const float* __restrict__ coeffs){
  __shared__ float2 G[2][2]; __shared__ int gs[128];
  int u=blockIdx.x;
  if(threadIdx.x==0){
    float a=coeffs[u*2],b=coeffs[u*2+1];
    float ca=cosf(.5f*a),sa=sinf(.5f*a),cb=cosf(.5f*b),sb=sinf(.5f*b);
    G[0][0]=make_float2(cb*ca, sb*sa);
    G[0][1]=make_float2(-sb*ca,-cb*sa);
    G[1][0]=make_float2( sb*ca,-cb*sa);
    G[1][1]=make_float2(cb*ca,-sb*sa);
  }
  if(threadIdx.x<128)gs[threadIdx.x]=d_g[threadIdx.x];
  __syncthreads();
  const float* Ar=A_re+(size_t)u*16384; const float* Ai=A_im+(size_t)u*16384;
  float2* C =d_qb+(size_t)u*16384;
  float2* Xa=d_qb+(size_t)(4+u)*16384;
  float2* GP=d_qb+(size_t)(16+u)*16384;
  for(int t=threadIdx.x;t<16384;t+=blockDim.x){
    int r=t>>7,c=t&127;
    float2 cc;
    cc.x=Ar[r*128+c]+Ar[c*128+r];
    cc.y=Ai[r*128+c]-Ai[c*128+r]+((r==c)?1.f:0.f);
    C[t]=cc;
    Xa[t]=make_float2(0.f,(r==c)?-1.f:0.f);
    int gi=gs[c];
    float2 p=make_float2(1.f,0.f);
    #pragma unroll
    for(int b_=0;b_<7;b_++)p=cmul(p,G[(gi>>b_)&1][(r>>b_)&1]);
    GP[t]=p;
  }
}

// tiled complex 128x128 GEMM on d_qb slots. grid (16, units). mode 1: OUT = 2*A - A@B
__global__ __launch_bounds__(256) void cgemm(int osl,int ost,int asl,int ast,int bsl,int bst,int mode){
  __shared__ float2 As[32][33];
  __shared__ float2 Bs[32][33];
  int u=blockIdx.y;
  const float2* Au=d_qb+(size_t)(asl+u*ast)*16384;
  const float2* Bu=d_qb+(size_t)(bsl+u*bst)*16384;
  float2* Ou=d_qb+(size_t)(osl+u*ost)*16384;
  int ti=(blockIdx.x>>2)*32, tj=(blockIdx.x&3)*32;
  int tx=threadIdx.x&15, ty=threadIdx.x>>4;
  float2 acc[2][2];
  #pragma unroll
  for(int i=0;i<2;i++)for(int j=0;j<2;j++)acc[i][j]=make_float2(0.f,0.f);
  for(int k0=0;k0<128;k0+=32){
    for(int t=threadIdx.x;t<1024;t+=256){
      int rr=t>>5, cc=t&31;
      As[rr][cc]=Au[(ti+rr)*128+k0+cc];
      Bs[rr][cc]=Bu[(k0+rr)*128+tj+cc];
    }
    __syncthreads();
    #pragma unroll
    for(int k=0;k<32;k++){
      float2 a0=As[ty*2][k],a1=As[ty*2+1][k];
      float2 b0=Bs[k][tx*2],b1=Bs[k][tx*2+1];
      cfma(acc[0][0],a0,b0); cfma(acc[0][1],a0,b1);
      cfma(acc[1][0],a1,b0); cfma(acc[1][1],a1,b1);
    }
    __syncthreads();
  }
  #pragma unroll
  for(int i=0;i<2;i++)
  #pragma unroll
  for(int j=0;j<2;j++){
    int gi=ti+ty*2+i, gj=tj+tx*2+j;
    float2 v=acc[i][j];
    if(mode==1){float2 xa=Au[gi*128+gj];v.x=2.f*xa.x-v.x;v.y=2.f*xa.y-v.y;}
    Ou[gi*128+gj]=v;
  }
}

__global__ void k_qT(int base){
  int u=blockIdx.y;
  const float2* X=d_qb+(size_t)(base+u)*16384;
  float2* Q=d_qb+(size_t)(12+u)*16384;
  int t=blockIdx.x*256+threadIdx.x; int r=t>>7,c=t&127;
  float2 xv=X[c*128+r];
  Q[t]=make_float2(((r==c)?1.f:0.f)+2.f*xv.y,-2.f*xv.x);
}

__global__ void k_Wl(const float* __restrict__ dec_w){
  int k=blockIdx.x,l=blockIdx.y,c=threadIdx.x;
  const float2* L=d_qb+(size_t)(16+l)*16384;
  const float* dw=dec_w+(size_t)l*16384;
  float s=0.f;
  for(int i=0;i<128;i++)s=fmaf(L[k*128+i].x,dw[i*128+c],s);
  d_Wl[l*16384+k*128+c]=s;
}

__global__ void k_radial(const int* __restrict__ ei,const float* __restrict__ x){
  int e=blockIdx.x*256+threadIdx.x;
  int r=ei[e],c=ei[Ee+e];
  float dx=x[r*3]-x[c*3],dy=x[r*3+1]-x[c*3+1],dz=x[r*3+2]-x[c*3+2];
  d_radial[e]=dx*dx+dy*dy+dz*dz;
}

__global__ void k_norm(){
  int row=blockIdx.x*8+(threadIdx.x>>5),lane=threadIdx.x&31;
  float4* p=(float4*)(d_qin+(size_t)row*128);
  float4 v=p[lane];
  float s=v.x*v.x+v.y*v.y+v.z*v.z+v.w*v.w;
  #pragma unroll
  for(int o=16;o;o>>=1)s+=__shfl_xor_sync(0xffffffffu,s,o);
  float inv=rsqrtf(s+1e-12f);
  v.x*=inv;v.y*=inv;v.z*=inv;v.w*=inv;
  p[lane]=v;
}

__global__ void k_finx(const float* __restrict__ x,float* __restrict__ o){
  int i=blockIdx.x*256+threadIdx.x;
  if(i<Nn*3)o[i]=x[i]+d_xacc[i];
}

#define NG_SMEM (66560+33792+512)
// out = [accum?out:0] + A@W + bias
__global__ __launch_bounds__(256) void node_gemm(float* __restrict__ out,const float* __restrict__ A,
    const float* __restrict__ W,const float* __restrict__ bias,int accum){
  extern __shared__ float sm[];
  ull* Ws=(ull*)sm;
  float* As=sm+16640;
  float* bs=As+8448;
  int tid=threadIdx.x,n0=blockIdx.x*64;
  for(int t=tid;t<8192;t+=256){int k=t>>6,jp=t&63;Ws[k*65+jp]=pk2(W[k*128+jp*2],W[k*128+jp*2+1]);}
  if(tid<128)bs[tid]=bias?bias[tid]:0.f;
  for(int t=tid;t<2048;t+=256){
    int rr=t>>5,c4=(t&31)*4,n=n0+rr; if(n>=Nn)n=Nn-1;
    float4 v=*(const float4*)&A[(size_t)n*128+c4];
    *(float4*)&As[rr*132+c4]=v;
  }
  __syncthreads();
  int cg=tid&15,rg=tid>>4;
  ull acc[4][4];
  #pragma unroll
  for(int i=0;i<4;i++)for(int j=0;j<4;j++)acc[i][j]=0ULL;
  #pragma unroll 4
  for(int k=0;k<128;k++){
    ull b0=Ws[k*65+cg],b1=Ws[k*65+cg+16],b2=Ws[k*65+cg+32],b3=Ws[k*65+cg+48];
    #pragma unroll
    for(int i=0;i<4;i++){
      float a=As[(rg*4+i)*132+k]; ull aa=pk2(a,a);
      fma2(acc[i][0],aa,b0);fma2(acc[i][1],aa,b1);fma2(acc[i][2],aa,b2);fma2(acc[i][3],aa,b3);
    }
  }
  #pragma unroll
  for(int i=0;i<4;i++){
    int n=n0+rg*4+i; if(n>=Nn)continue;
    float* op=out+(size_t)n*128;
    #pragma unroll
    for(int j=0;j<4;j++){
      int c0=2*(cg+16*j);
      float lo,hi;up2(acc[i][j],lo,hi);
      lo+=bs[c0];hi+=bs[c0+1];
      if(accum){lo+=op[c0];hi+=op[c0+1];}
      op[c0]=lo;op[c0+1]=hi;
    }
  }
}

#define KE_SMEM (104192)
// mode 0: agg += silu(silu(m1)@W2+b2)/100 ; mode 1: coord head -> d_xacc
__global__ __launch_bounds__(256) void k_edge(const int* __restrict__ ei,const float* __restrict__ ea,
    const float* __restrict__ wre,const float* __restrict__ b1,const float* __restrict__ W2,
    const float* __restrict__ b2,const float* __restrict__ cw3,const float* __restrict__ x,int mode){
  extern __shared__ float sm[];
  ull* W2s=(ull*)sm;
  float* m1s=sm+16640;
  float* swr=m1s+8448; float* swe=swr+128; float* sb1=swe+128; float* sb2=sb1+128; float* scw=sb2+128;
  float* srad=scw+128; float* sea=srad+64; float* tdot=sea+64;
  int* srow=(int*)(tdot+64); int* scol=srow+64;
  int tid=threadIdx.x,e0=blockIdx.x*64;
  for(int t=tid;t<8192;t+=256){int k=t>>6,jp=t&63;W2s[k*65+jp]=pk2(W2[k*128+jp*2],W2[k*128+jp*2+1]);}
  if(tid<128){swr[tid]=wre[tid];swe[tid]=wre[128+tid];sb1[tid]=b1[tid];sb2[tid]=b2[tid];scw[tid]=mode?cw3[tid]:0.f;}
  if(tid<64){int e=e0+tid;srow[tid]=ei[e];scol[tid]=ei[Ee+e];srad[tid]=d_radial[e];sea[tid]=ea[e];tdot[tid]=0.f;}
  __syncthreads();
  for(int t=tid;t<2048;t+=256){
    int e=t>>5,c4=(t&31)*4;
    float4 p1=*(const float4*)&d_P1[(size_t)srow[e]*128+c4];
    float4 p2=*(const float4*)&d_P2[(size_t)scol[e]*128+c4];
    float r_=srad[e],w_=sea[e];
    float4 o;
    o.x=siluf(p1.x+p2.x+r_*swr[c4  ]+w_*swe[c4  ]+sb1[c4  ]);
    o.y=siluf(p1.y+p2.y+r_*swr[c4+1]+w_*swe[c4+1]+sb1[c4+1]);
    o.z=siluf(p1.z+p2.z+r_*swr[c4+2]+w_*swe[c4+2]+sb1[c4+2]);
    o.w=siluf(p1.w+p2.w+r_*swr[c4+3]+w_*swe[c4+3]+sb1[c4+3]);
    *(float4*)&m1s[e*132+c4]=o;
  }
  __syncthreads();
  int cg=tid&15,rg=tid>>4;
  ull acc[4][4];
  #pragma unroll
  for(int i=0;i<4;i++)for(int j=0;j<4;j++)acc[i][j]=0ULL;
  #pragma unroll 4
  for(int k=0;k<128;k++){
    ull b0=W2s[k*65+cg],b1_=W2s[k*65+cg+16],b2_=W2s[k*65+cg+32],b3_=W2s[k*65+cg+48];
    #pragma unroll
    for(int i=0;i<4;i++){
      float a=m1s[(rg*4+i)*132+k]; ull aa=pk2(a,a);
      fma2(acc[i][0],aa,b0);fma2(acc[i][1],aa,b1_);fma2(acc[i][2],aa,b2_);fma2(acc[i][3],aa,b3_);
    }
  }
  if(mode==0){
    #pragma unroll
    for(int i=0;i<4;i++){
      float* ap=d_agg+(size_t)srow[rg*4+i]*128;
      #pragma unroll
      for(int j=0;j<4;j++){
        int c0=2*(cg+16*j);
        float lo,hi;up2(acc[i][j],lo,hi);
        lo=siluf(lo+sb2[c0])*0.01f; hi=siluf(hi+sb2[c0+1])*0.01f;
        red2(ap+c0,lo,hi);
      }
    }
  }else{
    #pragma unroll
    for(int i=0;i<4;i++){
      float p=0.f;
      #pragma unroll
      for(int j=0;j<4;j++){
        int c0=2*(cg+16*j);
        float lo,hi;up2(acc[i][j],lo,hi);
        p+=siluf(lo+sb2[c0])*scw[c0]+siluf(hi+sb2[c0+1])*scw[c0+1];
      }
      atomicAdd(&tdot[rg*4+i],p);
    }
    __syncthreads();
    if(tid<64){
      int row=srow[tid],col=scol[tid];
      float dx=x[row*3]-x[col*3],dy=x[row*3+1]-x[col*3+1],dz=x[row*3+2]-x[col*3+2];
      float inv=1.f/(sqrtf(srad[tid]+1e-8f)+1.f);
      float tv=tdot[tid]*0.01f*inv;
      atomicAdd(&d_xacc[row*3  ],dx*tv);
      atomicAdd(&d_xacc[row*3+1],dy*tv);
      atomicAdd(&d_xacc[row*3+2],dz*tv);
    }
  }
}

extern "C" void kernel_launch(void* const* d_in,const int* in_sizes,int n_in,void* d_out,int out_size){
  const float* h=(const float*)d_in[0];
  const float* x=(const float*)d_in[1];
  const int* ei=(const int*)d_in[2];
  const float* ea=(const float*)d_in[3];
  const float* e_w1=(const float*)d_in[4];
  const float* e_b1=(const float*)d_in[5];
  const float* e_w2=(const float*)d_in[6];
  const float* e_b2=(const float*)d_in[7];
  const float* enc_w=(const float*)d_in[8];
  const float* enc_b=(const float*)d_in[9];
  const float* coeffs=(const float*)d_in[10];
  const float* A_re=(const float*)d_in[11];
  const float* A_im=(const float*)d_in[12];
  const float* dec_w=(const float*)d_in[13];
  const float* dec_b=(const float*)d_in[14];
  const float* c_w1=(const float*)d_in[15];
  const float* c_b1=(const float*)d_in[16];
  const float* c_w2=(const float*)d_in[17];
  const float* c_b2=(const float*)d_in[18];
  const float* c_w3=(const float*)d_in[19];
  float* out=(float*)d_out;

  cudaFuncSetAttribute(node_gemm,cudaFuncAttributeMaxDynamicSharedMemorySize,NG_SMEM);
  cudaFuncSetAttribute(k_edge,cudaFuncAttributeMaxDynamicSharedMemorySize,KE_SMEM);

  float *ph,*pP1,*pP2,*pagg,*pqin,*pWl,*pxacc;
  cudaGetSymbolAddress((void**)&ph,d_h);
  cudaGetSymbolAddress((void**)&pP1,d_P1);
  cudaGetSymbolAddress((void**)&pP2,d_P2);
  cudaGetSymbolAddress((void**)&pagg,d_agg);
  cudaGetSymbolAddress((void**)&pqin,d_qin);
  cudaGetSymbolAddress((void**)&pWl,d_Wl);
  cudaGetSymbolAddress((void**)&pxacc,d_xacc);

  // non-kernel nodes first (memcpy/memset don't count as kernel launches for ncu -s)
  cudaMemcpyAsync(ph,h,(size_t)Nn*128*4,cudaMemcpyDeviceToDevice);
  cudaMemsetAsync(pagg,0,(size_t)Nn*128*4);
  cudaMemsetAsync(pxacc,0,(size_t)Nn*3*4);

  // launches 0-4, then k_edge at index 5 (ncu -s 5 -c 1 captures it)
  k_radial<<<1875,256>>>(ei,x);                                   // 0
  k_setup_perm<<<1,1>>>();                                        // 1
  k_build<<<4,256>>>(A_re,A_im,coeffs);                           // 2
  const float* w1_0=e_w1;
  node_gemm<<<469,256,NG_SMEM>>>(pP1,ph,w1_0,nullptr,0);          // 3
  node_gemm<<<469,256,NG_SMEM>>>(pP2,ph,w1_0+16384,nullptr,0);    // 4
  k_edge<<<7500,256,KE_SMEM>>>(ei,ea,w1_0+256*128,e_b1,e_w2,e_b2,nullptr,nullptr,0); // 5 <- profiled

  // ---- quantum setup (tiled cgemm, 4 Newton iters) ----
  int cur=4,nxt=8;
  for(int it=0;it<4;it++){
    cgemm<<<dim3(16,4),256>>>(12,1, 0,1, cur,1, 0);  // E = C@X
    cgemm<<<dim3(16,4),256>>>(nxt,1, cur,1, 12,1, 1);// Xn = 2X - X@E
    int t_=cur;cur=nxt;nxt=t_;
  }
  k_qT<<<dim3(64,4),256>>>(4+cur-4+4); // X in slot (4..7)+... cur==4 after even iters -> base 8? no: base slot index = 4+? see below
  // NOTE: cur is the slot GROUP start offset used in cgemm calls (cur=4 means slots 4..7).
  // After 4 iterations cur==4, so X lives in slots 4+u. k_qT(base=4).
  cgemm<<<dim3(16,4),256>>>(0,1, 12,1, 16,1, 0);     // T_u = qT @ GP
  cgemm<<<dim3(16,2),256>>>(16,1, 0,2, 1,2, 0);      // L_l = T_{2l} @ T_{2l+1}
  k_Wl<<<dim3(128,2),128>>>(dec_w);

  // ---- layer 0 tail ----
  node_gemm<<<469,256,NG_SMEM>>>(pqin,ph,enc_w,nullptr,0);
  node_gemm<<<469,256,NG_SMEM>>>(pqin,pagg,enc_w+16384,enc_b,1);
  k_norm<<<3750,256>>>();
  node_gemm<<<469,256,NG_SMEM>>>(ph,pqin,pWl,dec_b,1);

  // ---- layer 1 ----
  const float* w1_1=e_w1+(size_t)258*128;
  node_gemm<<<469,256,NG_SMEM>>>(pP1,ph,w1_1,nullptr,0);
  node_gemm<<<469,256,NG_SMEM>>>(pP2,ph,w1_1+16384,nullptr,0);
  cudaMemsetAsync(pagg,0,(size_t)Nn*128*4);
  k_edge<<<7500,256,KE_SMEM>>>(ei,ea,w1_1+256*128,e_b1+128,e_w2+16384,e_b2+128,nullptr,nullptr,0);
  node_gemm<<<469,256,NG_SMEM>>>(pqin,ph,enc_w+(size_t)256*128,nullptr,0);
  node_gemm<<<469,256,NG_SMEM>>>(pqin,pagg,enc_w+(size_t)256*128+16384,enc_b+128,1);
  k_norm<<<3750,256>>>();
  node_gemm<<<469,256,NG_SMEM>>>(ph,pqin,pWl+16384,dec_b+128,1);

  // ---- coordinate head ----
  node_gemm<<<469,256,NG_SMEM>>>(pP1,ph,c_w1,nullptr,0);
  node_gemm<<<469,256,NG_SMEM>>>(pP2,ph,c_w1+16384,nullptr,0);
  k_edge<<<7500,256,KE_SMEM>>>(ei,ea,c_w1+256*128,c_b1,c_w2,c_b2,c_w3,x,1);
  cudaMemcpyAsync(out,ph,(size_t)Nn*128*4,cudaMemcpyDeviceToDevice);
  k_finx<<<352,256>>>(x,out+(size_t)Nn*128);
}